// round 13
// baseline (speedup 1.0000x reference)
#include <cuda_runtime.h>
#include <stdint.h>

#define FRAMES   320
#define T_DIM    20
#define WW       256
#define HW       65536
#define WIN      7
#define OW       250
#define SUBS     20          // sub-bands per frame (10 bands x 2 halves)
#define WPB      4           // warps per block (consecutive sub-bands -> L1 halo reuse)
#define NUNITS   (FRAMES * SUBS)        // 6400 warps
#define NBLK     (NUNITS / WPB)         // 1600 blocks
#define TOTAL_PIX 20000000.0 // 320 * 250 * 250

typedef unsigned long long ull;

__device__ float g_part[T_DIM * 64];   // per-(t, b*4+chunk) partial maxes
__device__ double g_acc;
__device__ unsigned int g_done;

// ---------------------------------------------------------------- f32x2 helpers
__device__ __forceinline__ ull FMA2(ull a, ull b, ull c) {
    ull d; asm("fma.rn.f32x2 %0,%1,%2,%3;" : "=l"(d) : "l"(a), "l"(b), "l"(c)); return d;
}
__device__ __forceinline__ ull ADD2(ull a, ull b) {
    ull d; asm("add.rn.f32x2 %0,%1,%2;" : "=l"(d) : "l"(a), "l"(b)); return d;
}
__device__ __forceinline__ ull MUL2(ull a, ull b) {
    ull d; asm("mul.rn.f32x2 %0,%1,%2;" : "=l"(d) : "l"(a), "l"(b)); return d;
}
#define NEG2(a) ((a) ^ 0x8000000080000000ULL)
__device__ __forceinline__ ull PACK2(float lo, float hi) {
    ull d; asm("mov.b64 %0, {%1,%2};" : "=l"(d) : "f"(lo), "f"(hi)); return d;
}
__device__ __forceinline__ float LO2(ull a) {
    float f; asm("{ .reg .f32 h; mov.b64 {%0, h}, %1; }" : "=f"(f) : "l"(a)); return f;
}
__device__ __forceinline__ float HI2(ull a) {
    float f; asm("{ .reg .f32 l; mov.b64 {l, %0}, %1; }" : "=f"(f) : "l"(a)); return f;
}
__device__ __forceinline__ ull REP2(float v) { return PACK2(v, v); }

// ---------------------------------------------------------------- per-t partial max of Yt
__global__ __launch_bounds__(256) void max_kernel(const float* __restrict__ Yt) {
    int blk   = blockIdx.x;
    int chunk = blk & 3;
    int bt    = blk >> 2;            // b*T_DIM + t
    int t     = bt % T_DIM;
    int b     = bt / T_DIM;

    const float4* p = reinterpret_cast<const float4*>(Yt + (size_t)bt * HW)
                      + chunk * 4096 + threadIdx.x;
    float m = 0.0f;
#pragma unroll
    for (int i = 0; i < 16; ++i) {
        float4 v = p[i * 256];
        m = fmaxf(m, fmaxf(fmaxf(v.x, v.y), fmaxf(v.z, v.w)));
    }
#pragma unroll
    for (int o = 16; o; o >>= 1)
        m = fmaxf(m, __shfl_xor_sync(0xffffffffu, m, o));

    __shared__ float sm[8];
    if ((threadIdx.x & 31) == 0) sm[threadIdx.x >> 5] = m;
    __syncthreads();
    if (threadIdx.x == 0) {
        float mm = sm[0];
#pragma unroll
        for (int i = 1; i < 8; ++i) mm = fmaxf(mm, sm[i]);
        g_part[t * 64 + b * 4 + chunk] = mm;   // plain store, deterministic
        if (blk == 0) { g_acc = 0.0; g_done = 0u; }
    }
}

// ---------------------------------------------------------------- horizontal 7-window
__device__ __forceinline__ void hwin7p(const ull s[4], ull o[4]) {
    const float v0 = LO2(s[0]), v1 = HI2(s[0]), v2 = LO2(s[1]), v3 = HI2(s[1]);
    const float v4 = LO2(s[2]), v5 = HI2(s[2]), v6 = LO2(s[3]), v7 = HI2(s[3]);
    const float p1 = v0;
    const float p2 = p1 + v1;
    const float p3 = p2 + v2;
    const float p4 = p3 + v3;
    const float p5 = p4 + v4;
    const float p6 = p5 + v5;
    const float p7 = p6 + v6;
    const float p8 = p7 + v7;
    const float n1 = __shfl_down_sync(0xffffffffu, p1, 1);
    const float n2 = __shfl_down_sync(0xffffffffu, p2, 1);
    const float n3 = __shfl_down_sync(0xffffffffu, p3, 1);
    const float n4 = __shfl_down_sync(0xffffffffu, p4, 1);
    const float n5 = __shfl_down_sync(0xffffffffu, p5, 1);
    const float n6 = __shfl_down_sync(0xffffffffu, p6, 1);
    o[0] = PACK2(p7, p8 - p1);
    o[1] = PACK2((p8 - p2) + n1, (p8 - p3) + n2);
    o[2] = PACK2((p8 - p4) + n3, (p8 - p5) + n4);
    o[3] = PACK2((p8 - p6) + n5, v7 + n6);
}

// ---------------------------------------------------------------- main SSIM
// One warp = one (frame, sub-band). 20 sub-bands per frame: even -> 13 output
// rows, odd -> 12. Consecutive warps in a block share band halos in L1.
__global__ void __launch_bounds__(128, 7) ssim_kernel(const float* __restrict__ X,
                                                      const float* __restrict__ Y,
                                                      float* __restrict__ out) {
    const int warp = threadIdx.x >> 5;
    const int lane = threadIdx.x & 31;
    const int wg   = blockIdx.x * WPB + warp;   // 0..NUNITS-1
    const int frame = wg / SUBS;
    const int k     = wg % SUBS;                // sub-band index
    const int band  = k >> 1;
    const int half  = k & 1;
    const int row0  = band * 25 + (half ? 13 : 0);
    const int nin   = half ? 18 : 19;           // nout + 6
    const int t     = frame % T_DIM;
    const bool full = (lane != 31);  // lane 31: only j==0 columns (248,249) valid

    // per-t data_range from the 64 partial maxes
    float dm = fmaxf(g_part[t * 64 + lane], g_part[t * 64 + 32 + lane]);
#pragma unroll
    for (int o = 16; o; o >>= 1)
        dm = fmaxf(dm, __shfl_xor_sync(0xffffffffu, dm, o));
    const float dr = dm;
    float c1 = 0.01f * dr; c1 *= c1;
    float c2 = 0.03f * dr; c2 *= c2;
    const ull c1p = REP2(c1), c2p = REP2(c2);
    const ull kA1 = REP2(2.0f / 2401.0f);
    const ull kB1 = REP2(1.0f / 2401.0f);
    const ull kPA = REP2(1.0f / 24.0f);
    const ull kPB = REP2(-1.0f / 1176.0f);
    const ull kQA = REP2(1.0f / 48.0f);
    const ull kQB = REP2(-1.0f / 2352.0f);

    const size_t fbase = (size_t)frame * HW + (size_t)row0 * WW + (lane << 3);
    const double2* xp = reinterpret_cast<const double2*>(X + fbase);
    const double2* yp = reinterpret_cast<const double2*>(Y + fbase);

    ull sx[4], sy[4], sq[4], sp[4];
#pragma unroll
    for (int j = 0; j < 4; ++j) { sx[j] = 0ull; sy[j] = 0ull; sq[j] = 0ull; sp[j] = 0ull; }

    float acc = 0.f;   // accumulates (S - 1) per pixel

    // epilogue: staged for low register liveness
    auto epilogue = [&]() {
        ull P[4], Q[4];
        {
            ull hx[4], hy[4];
            hwin7p(sx, hx);
            hwin7p(sy, hy);
#pragma unroll
            for (int j = 0; j < 4; ++j) {
                P[j] = MUL2(hx[j], hy[j]);
                Q[j] = FMA2(hx[j], hx[j], MUL2(hy[j], hy[j]));
            }
        }
        ull A2[4];
        {
            ull hp[4];
            hwin7p(sp, hp);
#pragma unroll
            for (int j = 0; j < 4; ++j)
                A2[j] = FMA2(hp[j], kPA, FMA2(P[j], kPB, c2p));
        }
        ull B2[4];
        {
            ull hq[4];
            hwin7p(sq, hq);
#pragma unroll
            for (int j = 0; j < 4; ++j)
                B2[j] = FMA2(hq[j], kQA, FMA2(Q[j], kQB, c2p));
        }
#pragma unroll
        for (int j = 0; j < 4; ++j) {
            const ull A1 = FMA2(P[j], kA1, c1p);
            const ull B1 = FMA2(Q[j], kB1, c1p);
            const ull den  = MUL2(B1, B2[j]);
            const ull diff = FMA2(A1, A2[j], NEG2(den));   // num - den
            const float contrib = __fdividef(LO2(diff), LO2(den))
                                + __fdividef(HI2(diff), HI2(den));
            if (j == 0)      acc += contrib;
            else if (full)   acc += contrib;
        }
    };

    // prologue: rows 0..6, no subtract, no output
#pragma unroll
    for (int r = 0; r < WIN; ++r) {
        const double2 xa = xp[r * 32];
        const double2 xb = xp[r * 32 + 1];
        const double2 ya = yp[r * 32];
        const double2 yb = yp[r * 32 + 1];
        const ull nx[4] = { (ull)__double_as_longlong(xa.x), (ull)__double_as_longlong(xa.y),
                            (ull)__double_as_longlong(xb.x), (ull)__double_as_longlong(xb.y) };
        const ull ny[4] = { (ull)__double_as_longlong(ya.x), (ull)__double_as_longlong(ya.y),
                            (ull)__double_as_longlong(yb.x), (ull)__double_as_longlong(yb.y) };
#pragma unroll
        for (int j = 0; j < 4; ++j) {
            sx[j] = ADD2(sx[j], nx[j]);
            sy[j] = ADD2(sy[j], ny[j]);
            sq[j] = FMA2(nx[j], nx[j], FMA2(ny[j], ny[j], sq[j]));
            sp[j] = FMA2(nx[j], ny[j], sp[j]);
        }
    }

    // steady loop: rows 7..nin-1 (loads shadowed by previous row's epilogue)
#pragma unroll 1
    for (int r = WIN; r < nin; ++r) {
        const double2 xa = xp[r * 32];
        const double2 xb = xp[r * 32 + 1];
        const double2 ya = yp[r * 32];
        const double2 yb = yp[r * 32 + 1];
        const double2 xc = xp[(r - WIN) * 32];
        const double2 xd = xp[(r - WIN) * 32 + 1];
        const double2 yc = yp[(r - WIN) * 32];
        const double2 yd = yp[(r - WIN) * 32 + 1];

        epilogue();   // previous output row, in the loads' shadow

        const ull nx[4] = { (ull)__double_as_longlong(xa.x), (ull)__double_as_longlong(xa.y),
                            (ull)__double_as_longlong(xb.x), (ull)__double_as_longlong(xb.y) };
        const ull ny[4] = { (ull)__double_as_longlong(ya.x), (ull)__double_as_longlong(ya.y),
                            (ull)__double_as_longlong(yb.x), (ull)__double_as_longlong(yb.y) };
        const ull ox[4] = { (ull)__double_as_longlong(xc.x), (ull)__double_as_longlong(xc.y),
                            (ull)__double_as_longlong(xd.x), (ull)__double_as_longlong(xd.y) };
        const ull oy[4] = { (ull)__double_as_longlong(yc.x), (ull)__double_as_longlong(yc.y),
                            (ull)__double_as_longlong(yd.x), (ull)__double_as_longlong(yd.y) };
#pragma unroll
        for (int j = 0; j < 4; ++j) {
            const ull nxo = NEG2(ox[j]);     // sign-bit XOR on ALU pipe
            const ull nyo = NEG2(oy[j]);
            sx[j] = ADD2(sx[j], ADD2(nx[j], nxo));
            sy[j] = ADD2(sy[j], ADD2(ny[j], nyo));
            sq[j] = FMA2(nx[j], nx[j], FMA2(ny[j], ny[j],
                    FMA2(nxo, ox[j], FMA2(nyo, oy[j], sq[j]))));
            sp[j] = FMA2(nx[j], ny[j], FMA2(nxo, oy[j], sp[j]));
        }
    }
    epilogue();   // last output row

    // block reduction -> one double atomic per block, last block finalizes
    float v = acc;
#pragma unroll
    for (int o = 16; o; o >>= 1)
        v += __shfl_xor_sync(0xffffffffu, v, o);

    __shared__ float wsum[WPB];
    if (lane == 0) wsum[warp] = v;
    __syncthreads();
    if (threadIdx.x == 0) {
        float s = 0.f;
#pragma unroll
        for (int i = 0; i < WPB; ++i) s += wsum[i];
        atomicAdd(&g_acc, (double)s);
        __threadfence();
        unsigned int tick = atomicAdd(&g_done, 1u);
        if (tick == NBLK - 1) {           // last block: finalize
            __threadfence();
            double a = *((volatile double*)&g_acc);
            out[0] = (float)(-a / TOTAL_PIX);   // 1 - mean(S) = -mean(S-1)
        }
    }
}

// ---------------------------------------------------------------- launch
extern "C" void kernel_launch(void* const* d_in, const int* in_sizes, int n_in,
                              void* d_out, int out_size) {
    (void)in_sizes; (void)n_in; (void)out_size;
    const float* X = (const float*)d_in[0];
    const float* Y = (const float*)d_in[1];

    max_kernel<<<1280, 256>>>(Y);
    ssim_kernel<<<NBLK, WPB * 32>>>(X, Y, (float*)d_out);
}

// round 14
// speedup vs baseline: 2.2931x; 2.2931x over previous
#include <cuda_runtime.h>
#include <stdint.h>

#define FRAMES   320
#define T_DIM    20
#define WW       256
#define HW       65536
#define WIN      7
#define OW       250
#define BANDS    10
#define ORPB     25          // output rows per band
#define IRPB     31          // input rows per band (ORPB + WIN - 1)
#define WPB      4           // warps per block
#define NWARPS   (FRAMES * BANDS)       // 3200
#define NBLK     (NWARPS / WPB)         // 800
#define TOTAL_PIX 20000000.0 // 320 * 250 * 250

typedef unsigned long long ull;

__device__ float g_part[T_DIM * 64];   // per-(t, b*4+chunk) partial maxes
__device__ double g_acc;
__device__ unsigned int g_done;

// ---------------------------------------------------------------- f32x2 helpers
__device__ __forceinline__ ull FMA2(ull a, ull b, ull c) {
    ull d; asm("fma.rn.f32x2 %0,%1,%2,%3;" : "=l"(d) : "l"(a), "l"(b), "l"(c)); return d;
}
__device__ __forceinline__ ull ADD2(ull a, ull b) {
    ull d; asm("add.rn.f32x2 %0,%1,%2;" : "=l"(d) : "l"(a), "l"(b)); return d;
}
__device__ __forceinline__ ull MUL2(ull a, ull b) {
    ull d; asm("mul.rn.f32x2 %0,%1,%2;" : "=l"(d) : "l"(a), "l"(b)); return d;
}
#define NEG2(a) ((a) ^ 0x8000000080000000ULL)
__device__ __forceinline__ ull PACK2(float lo, float hi) {
    ull d; asm("mov.b64 %0, {%1,%2};" : "=l"(d) : "f"(lo), "f"(hi)); return d;
}
__device__ __forceinline__ float LO2(ull a) {
    float f; asm("{ .reg .f32 h; mov.b64 {%0, h}, %1; }" : "=f"(f) : "l"(a)); return f;
}
__device__ __forceinline__ float HI2(ull a) {
    float f; asm("{ .reg .f32 l; mov.b64 {l, %0}, %1; }" : "=f"(f) : "l"(a)); return f;
}
__device__ __forceinline__ ull REP2(float v) { return PACK2(v, v); }

// ---------------------------------------------------------------- per-t partial max of Yt
__global__ __launch_bounds__(256) void max_kernel(const float* __restrict__ Yt) {
    int blk   = blockIdx.x;
    int chunk = blk & 3;
    int bt    = blk >> 2;            // b*T_DIM + t
    int t     = bt % T_DIM;
    int b     = bt / T_DIM;

    const float4* p = reinterpret_cast<const float4*>(Yt + (size_t)bt * HW)
                      + chunk * 4096 + threadIdx.x;
    float m = 0.0f;
#pragma unroll
    for (int i = 0; i < 16; ++i) {
        float4 v = p[i * 256];
        m = fmaxf(m, fmaxf(fmaxf(v.x, v.y), fmaxf(v.z, v.w)));
    }
#pragma unroll
    for (int o = 16; o; o >>= 1)
        m = fmaxf(m, __shfl_xor_sync(0xffffffffu, m, o));

    __shared__ float sm[8];
    if ((threadIdx.x & 31) == 0) sm[threadIdx.x >> 5] = m;
    __syncthreads();
    if (threadIdx.x == 0) {
        float mm = sm[0];
#pragma unroll
        for (int i = 1; i < 8; ++i) mm = fmaxf(mm, sm[i]);
        g_part[t * 64 + b * 4 + chunk] = mm;   // plain store, deterministic
        if (blk == 0) { g_acc = 0.0; g_done = 0u; }
    }
}

// ---------------------------------------------------------------- horizontal 7-window
__device__ __forceinline__ void hwin7p(const ull s[4], ull o[4]) {
    const float v0 = LO2(s[0]), v1 = HI2(s[0]), v2 = LO2(s[1]), v3 = HI2(s[1]);
    const float v4 = LO2(s[2]), v5 = HI2(s[2]), v6 = LO2(s[3]), v7 = HI2(s[3]);
    const float p1 = v0;
    const float p2 = p1 + v1;
    const float p3 = p2 + v2;
    const float p4 = p3 + v3;
    const float p5 = p4 + v4;
    const float p6 = p5 + v5;
    const float p7 = p6 + v6;
    const float p8 = p7 + v7;
    const float n1 = __shfl_down_sync(0xffffffffu, p1, 1);
    const float n2 = __shfl_down_sync(0xffffffffu, p2, 1);
    const float n3 = __shfl_down_sync(0xffffffffu, p3, 1);
    const float n4 = __shfl_down_sync(0xffffffffu, p4, 1);
    const float n5 = __shfl_down_sync(0xffffffffu, p5, 1);
    const float n6 = __shfl_down_sync(0xffffffffu, p6, 1);
    o[0] = PACK2(p7, p8 - p1);
    o[1] = PACK2((p8 - p2) + n1, (p8 - p3) + n2);
    o[2] = PACK2((p8 - p4) + n3, (p8 - p5) + n4);
    o[3] = PACK2((p8 - p6) + n5, v7 + n6);
}

// ---------------------------------------------------------------- main SSIM
// One warp = one (frame, band). Rotated loop; epilogue de-staged for ILP:
// hx/hy/hp prefix+shuffle chains run concurrently, hq follows.
__global__ void __launch_bounds__(128, 6) ssim_kernel(const float* __restrict__ X,
                                                      const float* __restrict__ Y,
                                                      float* __restrict__ out) {
    const int warp = threadIdx.x >> 5;
    const int lane = threadIdx.x & 31;
    const int wg   = blockIdx.x * WPB + warp;   // 0..NWARPS-1
    const int frame = wg / BANDS;
    const int band  = wg % BANDS;
    const int t     = frame % T_DIM;
    const bool full = (lane != 31);  // lane 31: only j==0 columns (248,249) valid

    // per-t data_range from the 64 partial maxes
    float dm = fmaxf(g_part[t * 64 + lane], g_part[t * 64 + 32 + lane]);
#pragma unroll
    for (int o = 16; o; o >>= 1)
        dm = fmaxf(dm, __shfl_xor_sync(0xffffffffu, dm, o));
    const float dr = dm;
    float c1 = 0.01f * dr; c1 *= c1;
    float c2 = 0.03f * dr; c2 *= c2;
    const ull c1p = REP2(c1), c2p = REP2(c2);
    const ull kA1 = REP2(2.0f / 2401.0f);
    const ull kB1 = REP2(1.0f / 2401.0f);
    const ull kPA = REP2(1.0f / 24.0f);
    const ull kPB = REP2(-1.0f / 1176.0f);
    const ull kQA = REP2(1.0f / 48.0f);
    const ull kQB = REP2(-1.0f / 2352.0f);

    const size_t fbase = (size_t)frame * HW + (size_t)(band * ORPB) * WW + (lane << 3);
    const double2* xp = reinterpret_cast<const double2*>(X + fbase);
    const double2* yp = reinterpret_cast<const double2*>(Y + fbase);

    ull sx[4], sy[4], sq[4], sp[4];
#pragma unroll
    for (int j = 0; j < 4; ++j) { sx[j] = 0ull; sy[j] = 0ull; sq[j] = 0ull; sp[j] = 0ull; }

    float acc0 = 0.f, acc1 = 0.f;   // two (S-1) accumulators: halved add chain

    // epilogue: two-stage — hx/hy/hp concurrent (ILP 3), then hq
    auto epilogue = [&]() {
        ull P[4], Q[4], A2[4];
        {
            ull hx[4], hy[4], hp[4];
            hwin7p(sx, hx);
            hwin7p(sy, hy);
            hwin7p(sp, hp);
#pragma unroll
            for (int j = 0; j < 4; ++j) {
                P[j] = MUL2(hx[j], hy[j]);
                Q[j] = FMA2(hx[j], hx[j], MUL2(hy[j], hy[j]));
                A2[j] = FMA2(hp[j], kPA, FMA2(P[j], kPB, c2p));
            }
        }
        ull B2[4];
        {
            ull hq[4];
            hwin7p(sq, hq);
#pragma unroll
            for (int j = 0; j < 4; ++j)
                B2[j] = FMA2(hq[j], kQA, FMA2(Q[j], kQB, c2p));
        }
#pragma unroll
        for (int j = 0; j < 4; ++j) {
            const ull A1 = FMA2(P[j], kA1, c1p);
            const ull B1 = FMA2(Q[j], kB1, c1p);
            const ull den  = MUL2(B1, B2[j]);
            const ull diff = FMA2(A1, A2[j], NEG2(den));   // num - den
            const float contrib = __fdividef(LO2(diff), LO2(den))
                                + __fdividef(HI2(diff), HI2(den));
            if (j == 0)            acc0 += contrib;
            else if (full) {
                if (j & 1)         acc1 += contrib;
                else               acc0 += contrib;
            }
        }
    };

    // prologue: rows 0..6, no subtract, no output
#pragma unroll
    for (int r = 0; r < WIN; ++r) {
        const double2 xa = xp[r * 32];
        const double2 xb = xp[r * 32 + 1];
        const double2 ya = yp[r * 32];
        const double2 yb = yp[r * 32 + 1];
        const ull nx[4] = { (ull)__double_as_longlong(xa.x), (ull)__double_as_longlong(xa.y),
                            (ull)__double_as_longlong(xb.x), (ull)__double_as_longlong(xb.y) };
        const ull ny[4] = { (ull)__double_as_longlong(ya.x), (ull)__double_as_longlong(ya.y),
                            (ull)__double_as_longlong(yb.x), (ull)__double_as_longlong(yb.y) };
#pragma unroll
        for (int j = 0; j < 4; ++j) {
            sx[j] = ADD2(sx[j], nx[j]);
            sy[j] = ADD2(sy[j], ny[j]);
            sq[j] = FMA2(nx[j], nx[j], FMA2(ny[j], ny[j], sq[j]));
            sp[j] = FMA2(nx[j], ny[j], sp[j]);
        }
    }

    // steady loop: rows 7..30 (loads shadowed by previous row's epilogue)
#pragma unroll 1
    for (int r = WIN; r < IRPB; ++r) {
        const double2 xa = xp[r * 32];
        const double2 xb = xp[r * 32 + 1];
        const double2 ya = yp[r * 32];
        const double2 yb = yp[r * 32 + 1];
        const double2 xc = xp[(r - WIN) * 32];
        const double2 xd = xp[(r - WIN) * 32 + 1];
        const double2 yc = yp[(r - WIN) * 32];
        const double2 yd = yp[(r - WIN) * 32 + 1];

        epilogue();   // previous output row, in the loads' shadow

        const ull nx[4] = { (ull)__double_as_longlong(xa.x), (ull)__double_as_longlong(xa.y),
                            (ull)__double_as_longlong(xb.x), (ull)__double_as_longlong(xb.y) };
        const ull ny[4] = { (ull)__double_as_longlong(ya.x), (ull)__double_as_longlong(ya.y),
                            (ull)__double_as_longlong(yb.x), (ull)__double_as_longlong(yb.y) };
        const ull ox[4] = { (ull)__double_as_longlong(xc.x), (ull)__double_as_longlong(xc.y),
                            (ull)__double_as_longlong(xd.x), (ull)__double_as_longlong(xd.y) };
        const ull oy[4] = { (ull)__double_as_longlong(yc.x), (ull)__double_as_longlong(yc.y),
                            (ull)__double_as_longlong(yd.x), (ull)__double_as_longlong(yd.y) };
#pragma unroll
        for (int j = 0; j < 4; ++j) {
            const ull nxo = NEG2(ox[j]);     // sign-bit XOR on ALU pipe
            const ull nyo = NEG2(oy[j]);
            sx[j] = ADD2(sx[j], ADD2(nx[j], nxo));
            sy[j] = ADD2(sy[j], ADD2(ny[j], nyo));
            sq[j] = FMA2(nx[j], nx[j], FMA2(ny[j], ny[j],
                    FMA2(nxo, ox[j], FMA2(nyo, oy[j], sq[j]))));
            sp[j] = FMA2(nx[j], ny[j], FMA2(nxo, oy[j], sp[j]));
        }
    }
    epilogue();   // last output row (24)

    // block reduction -> one double atomic per block, last block finalizes
    float v = acc0 + acc1;
#pragma unroll
    for (int o = 16; o; o >>= 1)
        v += __shfl_xor_sync(0xffffffffu, v, o);

    __shared__ float wsum[WPB];
    if (lane == 0) wsum[warp] = v;
    __syncthreads();
    if (threadIdx.x == 0) {
        float s = 0.f;
#pragma unroll
        for (int i = 0; i < WPB; ++i) s += wsum[i];
        atomicAdd(&g_acc, (double)s);
        __threadfence();
        unsigned int tick = atomicAdd(&g_done, 1u);
        if (tick == NBLK - 1) {           // last block: finalize
            __threadfence();
            double a = *((volatile double*)&g_acc);
            out[0] = (float)(-a / TOTAL_PIX);   // 1 - mean(S) = -mean(S-1)
        }
    }
}

// ---------------------------------------------------------------- launch
extern "C" void kernel_launch(void* const* d_in, const int* in_sizes, int n_in,
                              void* d_out, int out_size) {
    (void)in_sizes; (void)n_in; (void)out_size;
    const float* X = (const float*)d_in[0];
    const float* Y = (const float*)d_in[1];

    max_kernel<<<1280, 256>>>(Y);
    ssim_kernel<<<NBLK, WPB * 32>>>(X, Y, (float*)d_out);
}

// round 15
// speedup vs baseline: 2.3756x; 1.0360x over previous
#include <cuda_runtime.h>
#include <stdint.h>

#define FRAMES   320
#define T_DIM    20
#define WW       256
#define HW       65536
#define WIN      7
#define OW       250
#define BANDS    10
#define ORPB     25          // output rows per band
#define IRPB     31          // input rows per band (ORPB + WIN - 1)
#define NWARPS   (FRAMES * BANDS)       // 3200 single-warp blocks
#define TOTAL_PIX 20000000.0 // 320 * 250 * 250

typedef unsigned long long ull;

__device__ float g_part[T_DIM * 64];   // per-(t, b*4+chunk) partial maxes
__device__ double g_acc;
__device__ unsigned int g_done;

// ---------------------------------------------------------------- f32x2 helpers
__device__ __forceinline__ ull FMA2(ull a, ull b, ull c) {
    ull d; asm("fma.rn.f32x2 %0,%1,%2,%3;" : "=l"(d) : "l"(a), "l"(b), "l"(c)); return d;
}
__device__ __forceinline__ ull ADD2(ull a, ull b) {
    ull d; asm("add.rn.f32x2 %0,%1,%2;" : "=l"(d) : "l"(a), "l"(b)); return d;
}
__device__ __forceinline__ ull MUL2(ull a, ull b) {
    ull d; asm("mul.rn.f32x2 %0,%1,%2;" : "=l"(d) : "l"(a), "l"(b)); return d;
}
#define NEG2(a) ((a) ^ 0x8000000080000000ULL)
__device__ __forceinline__ ull PACK2(float lo, float hi) {
    ull d; asm("mov.b64 %0, {%1,%2};" : "=l"(d) : "f"(lo), "f"(hi)); return d;
}
__device__ __forceinline__ float LO2(ull a) {
    float f; asm("{ .reg .f32 h; mov.b64 {%0, h}, %1; }" : "=f"(f) : "l"(a)); return f;
}
__device__ __forceinline__ float HI2(ull a) {
    float f; asm("{ .reg .f32 l; mov.b64 {l, %0}, %1; }" : "=f"(f) : "l"(a)); return f;
}
__device__ __forceinline__ ull REP2(float v) { return PACK2(v, v); }

// ---------------------------------------------------------------- per-t partial max of Yt
__global__ __launch_bounds__(256) void max_kernel(const float* __restrict__ Yt) {
    int blk   = blockIdx.x;
    int chunk = blk & 3;
    int bt    = blk >> 2;            // b*T_DIM + t
    int t     = bt % T_DIM;
    int b     = bt / T_DIM;

    const float4* p = reinterpret_cast<const float4*>(Yt + (size_t)bt * HW)
                      + chunk * 4096 + threadIdx.x;
    float m = 0.0f;
#pragma unroll
    for (int i = 0; i < 16; ++i) {
        float4 v = p[i * 256];
        m = fmaxf(m, fmaxf(fmaxf(v.x, v.y), fmaxf(v.z, v.w)));
    }
#pragma unroll
    for (int o = 16; o; o >>= 1)
        m = fmaxf(m, __shfl_xor_sync(0xffffffffu, m, o));

    __shared__ float sm[8];
    if ((threadIdx.x & 31) == 0) sm[threadIdx.x >> 5] = m;
    __syncthreads();
    if (threadIdx.x == 0) {
        float mm = sm[0];
#pragma unroll
        for (int i = 1; i < 8; ++i) mm = fmaxf(mm, sm[i]);
        g_part[t * 64 + b * 4 + chunk] = mm;   // plain store, deterministic
        if (blk == 0) { g_acc = 0.0; g_done = 0u; }
    }
}

// ---------------------------------------------------------------- horizontal 7-window
__device__ __forceinline__ void hwin7p(const ull s[4], ull o[4]) {
    const float v0 = LO2(s[0]), v1 = HI2(s[0]), v2 = LO2(s[1]), v3 = HI2(s[1]);
    const float v4 = LO2(s[2]), v5 = HI2(s[2]), v6 = LO2(s[3]), v7 = HI2(s[3]);
    const float p1 = v0;
    const float p2 = p1 + v1;
    const float p3 = p2 + v2;
    const float p4 = p3 + v3;
    const float p5 = p4 + v4;
    const float p6 = p5 + v5;
    const float p7 = p6 + v6;
    const float p8 = p7 + v7;
    const float n1 = __shfl_down_sync(0xffffffffu, p1, 1);
    const float n2 = __shfl_down_sync(0xffffffffu, p2, 1);
    const float n3 = __shfl_down_sync(0xffffffffu, p3, 1);
    const float n4 = __shfl_down_sync(0xffffffffu, p4, 1);
    const float n5 = __shfl_down_sync(0xffffffffu, p5, 1);
    const float n6 = __shfl_down_sync(0xffffffffu, p6, 1);
    o[0] = PACK2(p7, p8 - p1);
    o[1] = PACK2((p8 - p2) + n1, (p8 - p3) + n2);
    o[2] = PACK2((p8 - p4) + n3, (p8 - p5) + n4);
    o[3] = PACK2((p8 - p6) + n5, v7 + n6);
}

// ---------------------------------------------------------------- main SSIM
// Single-warp blocks, residency capped at 16/SM so the 7-row re-load window
// (16 x 14KB = 224KB) is L1-resident. Old-row loads use evict-first (.cs).
__global__ void __launch_bounds__(32, 16) ssim_kernel(const float* __restrict__ X,
                                                      const float* __restrict__ Y,
                                                      float* __restrict__ out) {
    const int lane = threadIdx.x;
    const int wg   = blockIdx.x;                // 0..NWARPS-1
    const int frame = wg / BANDS;
    const int band  = wg % BANDS;
    const int t     = frame % T_DIM;
    const bool full = (lane != 31);  // lane 31: only j==0 columns (248,249) valid

    // per-t data_range from the 64 partial maxes
    float dm = fmaxf(g_part[t * 64 + lane], g_part[t * 64 + 32 + lane]);
#pragma unroll
    for (int o = 16; o; o >>= 1)
        dm = fmaxf(dm, __shfl_xor_sync(0xffffffffu, dm, o));
    const float dr = dm;
    float c1 = 0.01f * dr; c1 *= c1;
    float c2 = 0.03f * dr; c2 *= c2;
    const ull c1p = REP2(c1), c2p = REP2(c2);
    const ull kA1 = REP2(2.0f / 2401.0f);
    const ull kB1 = REP2(1.0f / 2401.0f);
    const ull kPA = REP2(1.0f / 24.0f);
    const ull kPB = REP2(-1.0f / 1176.0f);
    const ull kQA = REP2(1.0f / 48.0f);
    const ull kQB = REP2(-1.0f / 2352.0f);

    const size_t fbase = (size_t)frame * HW + (size_t)(band * ORPB) * WW + (lane << 3);
    const double2* xp = reinterpret_cast<const double2*>(X + fbase);
    const double2* yp = reinterpret_cast<const double2*>(Y + fbase);

    ull sx[4], sy[4], sq[4], sp[4];
#pragma unroll
    for (int j = 0; j < 4; ++j) { sx[j] = 0ull; sy[j] = 0ull; sq[j] = 0ull; sp[j] = 0ull; }

    float acc0 = 0.f, acc1 = 0.f;   // two (S-1) accumulators

    // epilogue: two-stage — hx/hy/hp concurrent, then hq
    auto epilogue = [&]() {
        ull P[4], Q[4], A2[4];
        {
            ull hx[4], hy[4], hp[4];
            hwin7p(sx, hx);
            hwin7p(sy, hy);
            hwin7p(sp, hp);
#pragma unroll
            for (int j = 0; j < 4; ++j) {
                P[j] = MUL2(hx[j], hy[j]);
                Q[j] = FMA2(hx[j], hx[j], MUL2(hy[j], hy[j]));
                A2[j] = FMA2(hp[j], kPA, FMA2(P[j], kPB, c2p));
            }
        }
        ull B2[4];
        {
            ull hq[4];
            hwin7p(sq, hq);
#pragma unroll
            for (int j = 0; j < 4; ++j)
                B2[j] = FMA2(hq[j], kQA, FMA2(Q[j], kQB, c2p));
        }
#pragma unroll
        for (int j = 0; j < 4; ++j) {
            const ull A1 = FMA2(P[j], kA1, c1p);
            const ull B1 = FMA2(Q[j], kB1, c1p);
            const ull den  = MUL2(B1, B2[j]);
            const ull diff = FMA2(A1, A2[j], NEG2(den));   // num - den
            const float contrib = __fdividef(LO2(diff), LO2(den))
                                + __fdividef(HI2(diff), HI2(den));
            if (j == 0)            acc0 += contrib;
            else if (full) {
                if (j & 1)         acc1 += contrib;
                else               acc0 += contrib;
            }
        }
    };

    // prologue: rows 0..6, no subtract, no output
#pragma unroll
    for (int r = 0; r < WIN; ++r) {
        const double2 xa = xp[r * 32];
        const double2 xb = xp[r * 32 + 1];
        const double2 ya = yp[r * 32];
        const double2 yb = yp[r * 32 + 1];
        const ull nx[4] = { (ull)__double_as_longlong(xa.x), (ull)__double_as_longlong(xa.y),
                            (ull)__double_as_longlong(xb.x), (ull)__double_as_longlong(xb.y) };
        const ull ny[4] = { (ull)__double_as_longlong(ya.x), (ull)__double_as_longlong(ya.y),
                            (ull)__double_as_longlong(yb.x), (ull)__double_as_longlong(yb.y) };
#pragma unroll
        for (int j = 0; j < 4; ++j) {
            sx[j] = ADD2(sx[j], nx[j]);
            sy[j] = ADD2(sy[j], ny[j]);
            sq[j] = FMA2(nx[j], nx[j], FMA2(ny[j], ny[j], sq[j]));
            sp[j] = FMA2(nx[j], ny[j], sp[j]);
        }
    }

    // steady loop: rows 7..30 (loads shadowed by previous row's epilogue)
#pragma unroll 1
    for (int r = WIN; r < IRPB; ++r) {
        const double2 xa = xp[r * 32];
        const double2 xb = xp[r * 32 + 1];
        const double2 ya = yp[r * 32];
        const double2 yb = yp[r * 32 + 1];
        const double2 xc = __ldcs(&xp[(r - WIN) * 32]);       // dead after use:
        const double2 xd = __ldcs(&xp[(r - WIN) * 32 + 1]);   // evict-first
        const double2 yc = __ldcs(&yp[(r - WIN) * 32]);
        const double2 yd = __ldcs(&yp[(r - WIN) * 32 + 1]);

        epilogue();   // previous output row, in the loads' shadow

        const ull nx[4] = { (ull)__double_as_longlong(xa.x), (ull)__double_as_longlong(xa.y),
                            (ull)__double_as_longlong(xb.x), (ull)__double_as_longlong(xb.y) };
        const ull ny[4] = { (ull)__double_as_longlong(ya.x), (ull)__double_as_longlong(ya.y),
                            (ull)__double_as_longlong(yb.x), (ull)__double_as_longlong(yb.y) };
        const ull ox[4] = { (ull)__double_as_longlong(xc.x), (ull)__double_as_longlong(xc.y),
                            (ull)__double_as_longlong(xd.x), (ull)__double_as_longlong(xd.y) };
        const ull oy[4] = { (ull)__double_as_longlong(yc.x), (ull)__double_as_longlong(yc.y),
                            (ull)__double_as_longlong(yd.x), (ull)__double_as_longlong(yd.y) };
#pragma unroll
        for (int j = 0; j < 4; ++j) {
            const ull nxo = NEG2(ox[j]);     // sign-bit XOR on ALU pipe
            const ull nyo = NEG2(oy[j]);
            sx[j] = ADD2(sx[j], ADD2(nx[j], nxo));
            sy[j] = ADD2(sy[j], ADD2(ny[j], nyo));
            sq[j] = FMA2(nx[j], nx[j], FMA2(ny[j], ny[j],
                    FMA2(nxo, ox[j], FMA2(nyo, oy[j], sq[j]))));
            sp[j] = FMA2(nx[j], ny[j], FMA2(nxo, oy[j], sp[j]));
        }
    }
    epilogue();   // last output row (24)

    // warp reduction -> one double atomic per warp-block, last block finalizes
    float v = acc0 + acc1;
#pragma unroll
    for (int o = 16; o; o >>= 1)
        v += __shfl_xor_sync(0xffffffffu, v, o);

    if (lane == 0) {
        atomicAdd(&g_acc, (double)v);
        __threadfence();
        unsigned int tick = atomicAdd(&g_done, 1u);
        if (tick == NWARPS - 1) {         // last block: finalize
            __threadfence();
            double a = *((volatile double*)&g_acc);
            out[0] = (float)(-a / TOTAL_PIX);   // 1 - mean(S) = -mean(S-1)
        }
    }
}

// ---------------------------------------------------------------- launch
extern "C" void kernel_launch(void* const* d_in, const int* in_sizes, int n_in,
                              void* d_out, int out_size) {
    (void)in_sizes; (void)n_in; (void)out_size;
    const float* X = (const float*)d_in[0];
    const float* Y = (const float*)d_in[1];

    max_kernel<<<1280, 256>>>(Y);
    ssim_kernel<<<NWARPS, 32>>>(X, Y, (float*)d_out);
}